// round 6
// baseline (speedup 1.0000x reference)
#include <cuda_runtime.h>
#include <cstdint>

// ---------------- problem dims ----------------
#define BB 512
#define TT 64
#define HH 256     // hidden / obs dim
#define AA 6       // action dim
#define RR 256     // recurrent dim
#define KG 768     // 3*RR gate dim
#define LL 1024    // latent dim
#define NR 4       // rows per CTA in scan
#define NCTA 128   // BB / NR

// output layout: [deter | stoch | logits]
#define DET_OFF 0
#define ST_OFF  (BB * TT * RR)
#define LG_OFF  (BB * TT * RR + BB * TT * LL)

// ---------------- device scratch ----------------
__device__ __align__(16) float g_WcT[LL * KG];     // [c][k] fused stoch weights
__device__ __align__(16) float g_WcaT[AA * KG];    // [j][k] fused action weights
__device__ __align__(16) float g_bc[KG];           // b_ih + W_ih @ b_in
__device__ __align__(16) float g_WhhT[RR * KG];    // [j][k]
__device__ __align__(16) float g_WphT[RR * LL];    // [j][l]
__device__ __align__(16) float g_WpoT[HH * LL];    // [k][n]

// ---------------- packed fp32 helpers (FFMA2 path, PTX-only) ----------------
__device__ __forceinline__ void ffma2(float2& d, const float2 a, const float2 b) {
    asm("fma.rn.f32x2 %0, %1, %2, %0;"
        : "+l"(reinterpret_cast<unsigned long long&>(d))
        : "l"(reinterpret_cast<const unsigned long long&>(a)),
          "l"(reinterpret_cast<const unsigned long long&>(b)));
}
__device__ __forceinline__ void fadd2(float2& d, const float2 a) {
    asm("add.rn.f32x2 %0, %0, %1;"
        : "+l"(reinterpret_cast<unsigned long long&>(d))
        : "l"(reinterpret_cast<const unsigned long long&>(a)));
}

// ---------------- prep 1: fuse W_ih @ [W_in | b_in] ----------------
__global__ void prep_fuse(const float* __restrict__ W_in, const float* __restrict__ b_in,
                          const float* __restrict__ W_ih, const float* __restrict__ b_ih) {
    int idx = blockIdx.x * blockDim.x + threadIdx.x;
    if (idx >= KG * 1031) return;
    int k = idx / 1031;
    int c = idx % 1031;
    float acc = 0.f;
    if (c < 1030) {
        for (int h = 0; h < HH; ++h)
            acc = fmaf(W_ih[k * HH + h], W_in[h * 1030 + c], acc);
        if (c < LL) g_WcT[c * KG + k] = acc;
        else        g_WcaT[(c - LL) * KG + k] = acc;
    } else {
        for (int h = 0; h < HH; ++h)
            acc = fmaf(W_ih[k * HH + h], b_in[h], acc);
        g_bc[k] = acc + b_ih[k];
    }
}

// ---------------- prep 2: transposes ----------------
__global__ void prep_transpose(const float* __restrict__ W_hh, const float* __restrict__ W_post) {
    int idx = blockIdx.x * blockDim.x + threadIdx.x;
    const int T1 = KG * RR;
    const int T2 = LL * (RR + HH);
    if (idx < T1) {
        int k = idx / RR, j = idx % RR;
        g_WhhT[j * KG + k] = W_hh[idx];
    } else if (idx < T1 + T2) {
        int e = idx - T1;
        int l = e / (RR + HH), m = e % (RR + HH);
        float v = W_post[e];
        if (m < RR) g_WphT[m * LL + l] = v;
        else        g_WpoT[(m - RR) * LL + l] = v;
    }
}

// ---------------- obs GEMM: 128x128 tile, BK=8, 8x8 microtile, f32x2 ----------------
// out_logits[m][n] = b_post[n] + obs[m]·W_po[n].  M=32768, N=1024, K=256.
__global__ void __launch_bounds__(256) obs_gemm(const float* __restrict__ obs,
                                                const float* __restrict__ b_post,
                                                float* __restrict__ outL) {
    __shared__ float2 As2[8][128];   // duplicated {a,a}  (8 KB)
    __shared__ float  Bs[8][128];    // (4 KB)
    const int tid = threadIdx.x;
    const int bm = blockIdx.y * 128;
    const int bn = blockIdx.x * 128;
    const int ty = tid >> 4;         // 0..15 (m/8)
    const int tx = tid & 15;         // 0..15 (n/8)
    const int arow = tid >> 1;       // 0..127
    const int akq  = (tid & 1) * 4;  // 0 / 4
    const int bkk  = tid >> 5;       // 0..7
    const int bn4  = (tid & 31) * 4;

    float2 acc[8][4];
    #pragma unroll
    for (int i = 0; i < 8; ++i)
        #pragma unroll
        for (int j = 0; j < 4; ++j) acc[i][j] = make_float2(0.f, 0.f);

    for (int k0 = 0; k0 < HH; k0 += 8) {
        float4 av = *(const float4*)&obs[(size_t)(bm + arow) * HH + k0 + akq];
        As2[akq + 0][arow] = make_float2(av.x, av.x);
        As2[akq + 1][arow] = make_float2(av.y, av.y);
        As2[akq + 2][arow] = make_float2(av.z, av.z);
        As2[akq + 3][arow] = make_float2(av.w, av.w);
        float4 bv = *(const float4*)&g_WpoT[(size_t)(k0 + bkk) * LL + bn + bn4];
        *(float4*)&Bs[bkk][bn4] = bv;
        __syncthreads();
        #pragma unroll
        for (int kk = 0; kk < 8; ++kk) {
            float4 a01 = *(const float4*)&As2[kk][ty * 8 + 0];
            float4 a23 = *(const float4*)&As2[kk][ty * 8 + 2];
            float4 a45 = *(const float4*)&As2[kk][ty * 8 + 4];
            float4 a67 = *(const float4*)&As2[kk][ty * 8 + 6];
            float4 b03 = *(const float4*)&Bs[kk][tx * 8 + 0];
            float4 b47 = *(const float4*)&Bs[kk][tx * 8 + 4];
            float2 a[8] = { make_float2(a01.x, a01.y), make_float2(a01.z, a01.w),
                            make_float2(a23.x, a23.y), make_float2(a23.z, a23.w),
                            make_float2(a45.x, a45.y), make_float2(a45.z, a45.w),
                            make_float2(a67.x, a67.y), make_float2(a67.z, a67.w) };
            float2 b[4] = { make_float2(b03.x, b03.y), make_float2(b03.z, b03.w),
                            make_float2(b47.x, b47.y), make_float2(b47.z, b47.w) };
            #pragma unroll
            for (int i = 0; i < 8; ++i)
                #pragma unroll
                for (int j = 0; j < 4; ++j)
                    ffma2(acc[i][j], a[i], b[j]);
        }
        __syncthreads();
    }
    const int nb = bn + tx * 8;
    float4 bpA = *(const float4*)&b_post[nb];
    float4 bpB = *(const float4*)&b_post[nb + 4];
    #pragma unroll
    for (int i = 0; i < 8; ++i) {
        int m = bm + ty * 8 + i;
        float4 v0, v1;
        v0.x = acc[i][0].x + bpA.x; v0.y = acc[i][0].y + bpA.y;
        v0.z = acc[i][1].x + bpA.z; v0.w = acc[i][1].y + bpA.w;
        v1.x = acc[i][2].x + bpB.x; v1.y = acc[i][2].y + bpB.y;
        v1.z = acc[i][3].x + bpB.z; v1.w = acc[i][3].y + bpB.w;
        *(float4*)&outL[(size_t)m * LL + nb]     = v0;
        *(float4*)&outL[(size_t)m * LL + nb + 4] = v1;
    }
}

// ---------------- persistent scan: 512 threads, j-split halves, packed carry ----------------
__global__ void __launch_bounds__(512, 1) scan_kernel(
    const float* __restrict__ action,
    const unsigned int* __restrict__ first,
    const float* __restrict__ gumbel,       // [T][B][1024]
    const float* __restrict__ b_hh,
    float* __restrict__ out) {

    // pool holds gi|gh partials (24 KB); aliased by phase-2 logits partials (16 KB)
    __shared__ __align__(16) float s_pool[NR * KG * 2];
    // packed carry: s_detP[buf][j][8] = {r0,r0,r1,r1,r2,r2,r3,r3} (16 KB)
    __shared__ __align__(16) float s_detP[2][RR][8];
    __shared__ int   s_idx[NR][32];
    __shared__ float s_act[NR][AA];
    __shared__ int   s_reset[NR];

    float (*s_gi)[KG] = (float(*)[KG])s_pool;
    float (*s_gh)[KG] = (float(*)[KG])(s_pool + NR * KG);
    float (*s_lg)[LL] = (float(*)[LL])s_pool;

    const int tid = threadIdx.x;
    const int jh  = tid >> 8;      // j-half 0/1
    const int lk  = tid & 255;
    const int row0 = blockIdx.x * NR;
    int cur = 0;

    for (int t = 0; t < TT; ++t) {
        // ---- flags + action ----
        if (tid < NR) {
            unsigned f = first[(row0 + tid) * TT + t];
            s_reset[tid] = (t == 0) || (f != 0u);
        }
        if (tid >= 32 && tid < 32 + NR * AA) {
            int e = tid - 32;
            s_act[e / AA][e % AA] = action[((size_t)(row0 + e / AA) * TT + t) * AA + (e % AA)];
        }
        __syncthreads();

        // ---- zero carry on reset (each half zeroes its 2 rows) ----
        {
            int r0 = jh * 2, r1 = r0 + 1;
            if (s_reset[r0]) *(float2*)&s_detP[cur][lk][2 * r0] = make_float2(0.f, 0.f);
            if (s_reset[r1]) *(float2*)&s_detP[cur][lk][2 * r1] = make_float2(0.f, 0.f);
        }
        __syncthreads();

        // ---- phase 1: gi/gh partials (j-split). regs persist across syncs ----
        float2 gi[NR][2], gh[NR][2];
        if (lk < 192) {
            const int q4 = lk * 4;
            if (jh == 0) {
                float4 bc = *(const float4*)&g_bc[q4];
                float4 bh = *(const float4*)&b_hh[q4];
                #pragma unroll
                for (int r = 0; r < NR; ++r) {
                    gi[r][0] = make_float2(bc.x, bc.y); gi[r][1] = make_float2(bc.z, bc.w);
                    gh[r][0] = make_float2(bh.x, bh.y); gh[r][1] = make_float2(bh.z, bh.w);
                }
            } else {
                #pragma unroll
                for (int r = 0; r < NR; ++r) {
                    gi[r][0] = make_float2(0.f, 0.f); gi[r][1] = make_float2(0.f, 0.f);
                    gh[r][0] = make_float2(0.f, 0.f); gh[r][1] = make_float2(0.f, 0.f);
                }
                // action contribution (jh1 only)
                #pragma unroll
                for (int j = 0; j < AA; ++j) {
                    float4 w = *(const float4*)&g_WcaT[j * KG + q4];
                    float2 wl = make_float2(w.x, w.y), wh2 = make_float2(w.z, w.w);
                    #pragma unroll
                    for (int r = 0; r < NR; ++r) {
                        float a = s_act[r][j];
                        ffma2(gi[r][0], make_float2(a, a), wl);
                        ffma2(gi[r][1], make_float2(a, a), wh2);
                    }
                }
            }
            // one-hot gather: each half handles its own 2 rows
            #pragma unroll
            for (int rr2 = 0; rr2 < 2; ++rr2) {
                int r = jh * 2 + rr2;
                if (!s_reset[r]) {
                    #pragma unroll 8
                    for (int g = 0; g < 32; ++g) {
                        int c = (g << 5) + s_idx[r][g];
                        float4 w = *(const float4*)&g_WcT[c * KG + q4];
                        fadd2(gi[r][0], make_float2(w.x, w.y));
                        fadd2(gi[r][1], make_float2(w.z, w.w));
                    }
                }
            }
            // recurrent GEMV over this thread's j-half (packed det: 2 LDS.128 per j)
            const float* wb = &g_WhhT[(jh * 128) * KG + q4];
            const float* dpb = &s_detP[cur][jh * 128][0];
            #pragma unroll 8
            for (int jj = 0; jj < 128; ++jj) {
                float4 w = *(const float4*)(wb + (size_t)jj * KG);
                float2 wl = make_float2(w.x, w.y), wh2 = make_float2(w.z, w.w);
                float4 dA = *(const float4*)(dpb + jj * 8);      // r0,r0,r1,r1
                float4 dB = *(const float4*)(dpb + jj * 8 + 4);  // r2,r2,r3,r3
                ffma2(gh[0][0], make_float2(dA.x, dA.y), wl);
                ffma2(gh[0][1], make_float2(dA.x, dA.y), wh2);
                ffma2(gh[1][0], make_float2(dA.z, dA.w), wl);
                ffma2(gh[1][1], make_float2(dA.z, dA.w), wh2);
                ffma2(gh[2][0], make_float2(dB.x, dB.y), wl);
                ffma2(gh[2][1], make_float2(dB.x, dB.y), wh2);
                ffma2(gh[3][0], make_float2(dB.z, dB.w), wl);
                ffma2(gh[3][1], make_float2(dB.z, dB.w), wh2);
            }
            if (jh == 0) {
                #pragma unroll
                for (int r = 0; r < NR; ++r) {
                    *(float2*)&s_gi[r][q4]     = gi[r][0];
                    *(float2*)&s_gi[r][q4 + 2] = gi[r][1];
                    *(float2*)&s_gh[r][q4]     = gh[r][0];
                    *(float2*)&s_gh[r][q4 + 2] = gh[r][1];
                }
            }
        }
        __syncthreads();
        if (jh == 1 && lk < 192) {     // add jh1 partial in place
            const int q4 = lk * 4;
            #pragma unroll
            for (int r = 0; r < NR; ++r) {
                float2 a0 = *(float2*)&s_gi[r][q4],     a1 = *(float2*)&s_gi[r][q4 + 2];
                float2 b0 = *(float2*)&s_gh[r][q4],     b1 = *(float2*)&s_gh[r][q4 + 2];
                fadd2(a0, gi[r][0]); fadd2(a1, gi[r][1]);
                fadd2(b0, gh[r][0]); fadd2(b1, gh[r][1]);
                *(float2*)&s_gi[r][q4] = a0;     *(float2*)&s_gi[r][q4 + 2] = a1;
                *(float2*)&s_gh[r][q4] = b0;     *(float2*)&s_gh[r][q4 + 2] = b1;
            }
        }
        __syncthreads();

        // ---- GRU pointwise: u = lk, each half does its 2 rows ----
        {
            const int u = lk;
            #pragma unroll
            for (int rr2 = 0; rr2 < 2; ++rr2) {
                int r = jh * 2 + rr2;
                float ir = s_gi[r][u],       hr = s_gh[r][u];
                float iz = s_gi[r][u + 256], hz = s_gh[r][u + 256];
                float in_ = s_gi[r][u + 512], hn = s_gh[r][u + 512];
                float rg = 1.f / (1.f + expf(-(ir + hr)));
                float z  = 1.f / (1.f + expf(-(iz + hz)));
                float n  = tanhf(fmaf(rg, hn, in_));
                float dp = s_detP[cur][u][2 * r];
                float h  = (1.f - z) * n + z * dp;
                *(float2*)&s_detP[cur ^ 1][u][2 * r] = make_float2(h, h);
                out[DET_OFF + ((size_t)(row0 + r) * TT + t) * RR + u] = h;
            }
        }
        __syncthreads();

        // ---- phase 2: logits partials (j-split over h, packed det) ----
        float2 acc[NR][2];
        {
            const int q4 = lk * 4;
            if (jh == 0) {
                #pragma unroll
                for (int r = 0; r < NR; ++r) {
                    size_t bt = (size_t)(row0 + r) * TT + t;
                    float4 v = *(const float4*)&out[LG_OFF + bt * LL + q4]; // obs part + b_post
                    acc[r][0] = make_float2(v.x, v.y); acc[r][1] = make_float2(v.z, v.w);
                }
            } else {
                #pragma unroll
                for (int r = 0; r < NR; ++r) {
                    acc[r][0] = make_float2(0.f, 0.f); acc[r][1] = make_float2(0.f, 0.f);
                }
            }
            const float* wb = &g_WphT[(jh * 128) * LL + q4];
            const float* dpb = &s_detP[cur ^ 1][jh * 128][0];
            #pragma unroll 8
            for (int jj = 0; jj < 128; ++jj) {
                float4 w = *(const float4*)(wb + (size_t)jj * LL);
                float2 wl = make_float2(w.x, w.y), wh2 = make_float2(w.z, w.w);
                float4 dA = *(const float4*)(dpb + jj * 8);
                float4 dB = *(const float4*)(dpb + jj * 8 + 4);
                ffma2(acc[0][0], make_float2(dA.x, dA.y), wl);
                ffma2(acc[0][1], make_float2(dA.x, dA.y), wh2);
                ffma2(acc[1][0], make_float2(dA.z, dA.w), wl);
                ffma2(acc[1][1], make_float2(dA.z, dA.w), wh2);
                ffma2(acc[2][0], make_float2(dB.x, dB.y), wl);
                ffma2(acc[2][1], make_float2(dB.x, dB.y), wh2);
                ffma2(acc[3][0], make_float2(dB.z, dB.w), wl);
                ffma2(acc[3][1], make_float2(dB.z, dB.w), wh2);
            }
            if (jh == 0) {    // stash partial in s_lg (aliases gi/gh pool — consumed)
                #pragma unroll
                for (int r = 0; r < NR; ++r) {
                    *(float2*)&s_lg[r][q4]     = acc[r][0];
                    *(float2*)&s_lg[r][q4 + 2] = acc[r][1];
                }
            }
        }
        __syncthreads();

        // ---- combine + argmax + one-hot (jh1 threads only) ----
        if (jh == 1) {
            const int q4 = lk * 4;
            #pragma unroll
            for (int r = 0; r < NR; ++r) {
                size_t bt = (size_t)(row0 + r) * TT + t;
                float4 p = *(const float4*)&s_lg[r][q4];
                float4 lg;
                lg.x = acc[r][0].x + p.x; lg.y = acc[r][0].y + p.y;
                lg.z = acc[r][1].x + p.z; lg.w = acc[r][1].y + p.w;
                *(float4*)&out[LG_OFF + bt * LL + q4] = lg;
                float4 g4 = *(const float4*)&gumbel[((size_t)t * BB + row0 + r) * LL + q4];
                float v0 = lg.x + g4.x, v1 = lg.y + g4.y;
                float v2 = lg.z + g4.z, v3 = lg.w + g4.w;
                float bv = v0; int bi = q4;
                if (v1 > bv) { bv = v1; bi = q4 + 1; }
                if (v2 > bv) { bv = v2; bi = q4 + 2; }
                if (v3 > bv) { bv = v3; bi = q4 + 3; }
                #pragma unroll
                for (int off = 1; off < 8; off <<= 1) {
                    float ov = __shfl_xor_sync(0xffffffffu, bv, off);
                    int   oi = __shfl_xor_sync(0xffffffffu, bi, off);
                    if (ov > bv || (ov == bv && oi < bi)) { bv = ov; bi = oi; }
                }
                float4 sv;
                sv.x = (q4 + 0 == bi) ? 1.f : 0.f;
                sv.y = (q4 + 1 == bi) ? 1.f : 0.f;
                sv.z = (q4 + 2 == bi) ? 1.f : 0.f;
                sv.w = (q4 + 3 == bi) ? 1.f : 0.f;
                *(float4*)&out[ST_OFF + bt * LL + q4] = sv;
                if ((lk & 7) == 0) s_idx[r][lk >> 3] = bi & 31;
            }
        }
        __syncthreads();
        cur ^= 1;
    }
}

// ---------------- launcher ----------------
extern "C" void kernel_launch(void* const* d_in, const int* in_sizes, int n_in,
                              void* d_out, int out_size) {
    const float* obs          = (const float*)d_in[0];
    const float* action       = (const float*)d_in[1];
    const unsigned int* first = (const unsigned int*)d_in[2];
    const float* gumbel       = (const float*)d_in[3];
    const float* W_in         = (const float*)d_in[4];
    const float* b_in         = (const float*)d_in[5];
    const float* W_ih         = (const float*)d_in[6];
    const float* W_hh         = (const float*)d_in[7];
    const float* b_ih         = (const float*)d_in[8];
    const float* b_hh         = (const float*)d_in[9];
    const float* W_post       = (const float*)d_in[10];
    const float* b_post       = (const float*)d_in[11];
    float* out = (float*)d_out;
    (void)in_sizes; (void)n_in; (void)out_size;

    prep_fuse<<<(KG * 1031 + 255) / 256, 256>>>(W_in, b_in, W_ih, b_ih);
    prep_transpose<<<(KG * RR + LL * (RR + HH) + 255) / 256, 256>>>(W_hh, W_post);
    dim3 ggrid(LL / 128, (BB * TT) / 128);
    obs_gemm<<<ggrid, 256>>>(obs, b_post, out + LG_OFF);
    scan_kernel<<<NCTA, 512>>>(action, first, gumbel, b_hh, out);
}

// round 7
// speedup vs baseline: 1.0737x; 1.0737x over previous
#include <cuda_runtime.h>
#include <cooperative_groups.h>
#include <cstdint>

namespace cg = cooperative_groups;

// ---------------- problem dims ----------------
#define BB 512
#define TT 64
#define HH 256     // hidden / obs dim
#define AA 6       // action dim
#define RR 256     // recurrent dim
#define KG 768     // 3*RR gate dim
#define LL 1024    // latent dim
#define NCTA 128   // CTAs (64 clusters of 2); each cluster owns 8 rows, each CTA owns 4

// output layout: [deter | stoch | logits]
#define DET_OFF 0
#define ST_OFF  (BB * TT * RR)
#define LG_OFF  (BB * TT * RR + BB * TT * LL)

// ---------------- device scratch ----------------
__device__ __align__(16) float g_WcT[LL * KG];     // [c][k] fused stoch weights
__device__ __align__(16) float g_WcaT[AA * KG];    // [j][k] fused action weights
__device__ __align__(16) float g_bc[KG];           // b_ih + W_ih @ b_in
__device__ __align__(16) float g_WhhT[RR * KG];    // [j][k]
__device__ __align__(16) float g_WphT[RR * LL];    // [j][l]
__device__ __align__(16) float g_WpoT[HH * LL];    // [k][n]

// ---------------- packed fp32 helpers (FFMA2 path) ----------------
__device__ __forceinline__ void ffma2(float2& d, const float2 a, const float2 b) {
    asm("fma.rn.f32x2 %0, %1, %2, %0;"
        : "+l"(reinterpret_cast<unsigned long long&>(d))
        : "l"(reinterpret_cast<const unsigned long long&>(a)),
          "l"(reinterpret_cast<const unsigned long long&>(b)));
}

// ---------------- prep 1: fuse W_ih @ [W_in | b_in] ----------------
__global__ void prep_fuse(const float* __restrict__ W_in, const float* __restrict__ b_in,
                          const float* __restrict__ W_ih, const float* __restrict__ b_ih) {
    int idx = blockIdx.x * blockDim.x + threadIdx.x;
    if (idx >= KG * 1031) return;
    int k = idx / 1031;
    int c = idx % 1031;
    float acc = 0.f;
    if (c < 1030) {
        for (int h = 0; h < HH; ++h)
            acc = fmaf(W_ih[k * HH + h], W_in[h * 1030 + c], acc);
        if (c < LL) g_WcT[c * KG + k] = acc;
        else        g_WcaT[(c - LL) * KG + k] = acc;
    } else {
        for (int h = 0; h < HH; ++h)
            acc = fmaf(W_ih[k * HH + h], b_in[h], acc);
        g_bc[k] = acc + b_ih[k];
    }
}

// ---------------- prep 2: transposes ----------------
__global__ void prep_transpose(const float* __restrict__ W_hh, const float* __restrict__ W_post) {
    int idx = blockIdx.x * blockDim.x + threadIdx.x;
    const int T1 = KG * RR;
    const int T2 = LL * (RR + HH);
    if (idx < T1) {
        int k = idx / RR, j = idx % RR;
        g_WhhT[j * KG + k] = W_hh[idx];
    } else if (idx < T1 + T2) {
        int e = idx - T1;
        int l = e / (RR + HH), m = e % (RR + HH);
        float v = W_post[e];
        if (m < RR) g_WphT[m * LL + l] = v;
        else        g_WpoT[(m - RR) * LL + l] = v;
    }
}

// ---------------- obs GEMM (proven round-5 version: 128x64, BK=16, f32x2) ----------------
__global__ void __launch_bounds__(256) obs_gemm(const float* __restrict__ obs,
                                                const float* __restrict__ b_post,
                                                float* __restrict__ outL) {
    __shared__ float2 As2[128][17];   // duplicated {a,a}
    __shared__ float  Bs[16][64];
    int tid = threadIdx.x;
    int bm = blockIdx.y * 128;
    int bn = blockIdx.x * 64;
    int ty = tid >> 4;
    int tx = tid & 15;
    float2 acc2[8][2];
    #pragma unroll
    for (int i = 0; i < 8; ++i) { acc2[i][0] = make_float2(0.f, 0.f); acc2[i][1] = make_float2(0.f, 0.f); }

    for (int k0 = 0; k0 < HH; k0 += 16) {
        #pragma unroll
        for (int i = 0; i < 2; ++i) {
            int f = tid + i * 256;
            int row = f >> 2;
            int kp = (f & 3) * 4;
            float4 v = *(const float4*)&obs[(size_t)(bm + row) * HH + k0 + kp];
            As2[row][kp + 0] = make_float2(v.x, v.x);
            As2[row][kp + 1] = make_float2(v.y, v.y);
            As2[row][kp + 2] = make_float2(v.z, v.z);
            As2[row][kp + 3] = make_float2(v.w, v.w);
        }
        #pragma unroll
        for (int i = 0; i < 4; ++i) {
            int e = tid + i * 256;
            int kk = e >> 6;
            int n = e & 63;
            Bs[kk][n] = g_WpoT[(k0 + kk) * LL + bn + n];
        }
        __syncthreads();
        #pragma unroll
        for (int kk = 0; kk < 16; ++kk) {
            float2 b0 = *(const float2*)&Bs[kk][tx * 4];
            float2 b1 = *(const float2*)&Bs[kk][tx * 4 + 2];
            #pragma unroll
            for (int i = 0; i < 8; ++i) {
                float2 a2 = As2[ty * 8 + i][kk];
                ffma2(acc2[i][0], a2, b0);
                ffma2(acc2[i][1], a2, b1);
            }
        }
        __syncthreads();
    }
    float bp0 = b_post[bn + tx * 4], bp1 = b_post[bn + tx * 4 + 1];
    float bp2 = b_post[bn + tx * 4 + 2], bp3 = b_post[bn + tx * 4 + 3];
    #pragma unroll
    for (int i = 0; i < 8; ++i) {
        int m = bm + ty * 8 + i;
        float4 v;
        v.x = acc2[i][0].x + bp0; v.y = acc2[i][0].y + bp1;
        v.z = acc2[i][1].x + bp2; v.w = acc2[i][1].y + bp3;
        *(float4*)&outL[(size_t)m * LL + bn + tx * 4] = v;
    }
}

// ---------------- cluster-2 persistent scan ----------------
// Cluster pair owns 8 rows. Each CTA streams HALF the j-columns (j in [rank*128, rank*128+128))
// of W_hh and W_ph, computes that partial for all 8 rows, exchanges partials via DSMEM.
// Dynamic smem layout (floats):
//   s_gi     [4][768]       own-row input gates (bias + action + one-hot gather)
//   s_gh8    [8][768]       this CTA's j-slice gh partial, all 8 rows
//   s_ghr    [4][768]       peer's gh partial for MY rows (remote-written by peer)
//   s_det8   [2][128][16]   det slice j in my range, 8 rows duplicated {r,r} pairs
//   s_detown [2][4][256]    full det for own rows (GRU carry)
//   s_lg8    [8][1024]      this CTA's logits partial, all 8 rows
//   s_lgr    [4][1024]      peer's logits partial for MY rows
#define OFF_GI     0
#define OFF_GH8    3072
#define OFF_GHR    9216
#define OFF_DET8   12288
#define OFF_DETOWN 16384
#define OFF_LG8    18432
#define OFF_LGR    26624
#define SMEM_FLOATS 30720

__global__ void __launch_bounds__(512, 1) __cluster_dims__(2, 1, 1)
scan_kernel(const float* __restrict__ action,
            const unsigned int* __restrict__ first,
            const float* __restrict__ gumbel,       // [T][B][1024]
            const float* __restrict__ b_hh,
            float* __restrict__ out) {

    extern __shared__ float smem[];
    float* s_gi     = smem + OFF_GI;
    float* s_gh8    = smem + OFF_GH8;
    float* s_ghr    = smem + OFF_GHR;
    float* s_det8   = smem + OFF_DET8;
    float* s_detown = smem + OFF_DETOWN;
    float* s_lg8    = smem + OFF_LG8;
    float* s_lgr    = smem + OFF_LGR;
    __shared__ int   s_idx[4][32];
    __shared__ float s_act[4][AA];
    __shared__ int   s_reset[8];

    cg::cluster_group cluster = cg::this_cluster();
    const int rank = (int)cluster.block_rank();
    float* p_ghr  = (float*)cluster.map_shared_rank(s_ghr,  rank ^ 1);
    float* p_det8 = (float*)cluster.map_shared_rank(s_det8, rank ^ 1);
    float* p_lgr  = (float*)cluster.map_shared_rank(s_lgr,  rank ^ 1);

    const int tid = threadIdx.x;
    const int jh  = tid >> 8;        // intra-CTA jj-half
    const int lk  = tid & 255;
    const int pair  = blockIdx.x >> 1;
    const int prow0 = pair * 8;              // pair-global row base
    const int orow0 = prow0 + rank * 4;      // own rows base
    const int Jbase = rank * 128;            // this CTA's j slice
    int cur = 0;

    for (int t = 0; t < TT; ++t) {
        // ---- 1. flags (all 8 rows) + action (own rows) ----
        if (tid < 8) {
            unsigned f = first[(prow0 + tid) * TT + t];
            s_reset[tid] = (t == 0) || (f != 0u);
        }
        if (tid >= 32 && tid < 32 + 4 * AA) {
            int e = tid - 32;
            s_act[e / AA][e % AA] = action[((size_t)(orow0 + e / AA) * TT + t) * AA + (e % AA)];
        }
        __syncthreads();

        // ---- 3. zero carries on reset ----
        #pragma unroll
        for (int k = 0; k < 2; ++k) {
            int idx = tid + k * 512;       // 1024 items: det8 slice
            int jj = idx >> 3, g = idx & 7;
            if (s_reset[g])
                *(float2*)&s_det8[cur * 2048 + jj * 16 + 2 * g] = make_float2(0.f, 0.f);
        }
        #pragma unroll
        for (int k = 0; k < 2; ++k) {
            int idx = tid + k * 512;       // 1024 items: detown
            int r = idx >> 8, u = idx & 255;
            if (s_reset[rank * 4 + r])
                s_detown[cur * 1024 + r * 256 + u] = 0.f;
        }
        __syncthreads();

        // ---- 5. gi for own rows (bias + action + one-hot gather) ----
        for (int item = tid; item < 4 * 192; item += 512) {
            int r = item / 192;
            int q = (item % 192) * 4;
            float4 a4 = *(const float4*)&g_bc[q];
            #pragma unroll
            for (int j = 0; j < AA; ++j) {
                float av = s_act[r][j];
                float4 w = *(const float4*)&g_WcaT[j * KG + q];
                a4.x = fmaf(av, w.x, a4.x); a4.y = fmaf(av, w.y, a4.y);
                a4.z = fmaf(av, w.z, a4.z); a4.w = fmaf(av, w.w, a4.w);
            }
            if (!s_reset[rank * 4 + r]) {
                #pragma unroll 8
                for (int g = 0; g < 32; ++g) {
                    int c = (g << 5) + s_idx[r][g];
                    float4 w = *(const float4*)&g_WcT[c * KG + q];
                    a4.x += w.x; a4.y += w.y; a4.z += w.z; a4.w += w.w;
                }
            }
            *(float4*)&s_gi[r * KG + q] = a4;
        }

        // ---- 6. phase 1: gh partial over my j-slice (jh splits jj 64/64, 8 rows) ----
        float2 gh[8][2];
        if (lk < 192) {
            const int q4 = lk * 4;
            if (rank == 0 && jh == 0) {
                float4 bh = *(const float4*)&b_hh[q4];
                #pragma unroll
                for (int g = 0; g < 8; ++g) {
                    gh[g][0] = make_float2(bh.x, bh.y);
                    gh[g][1] = make_float2(bh.z, bh.w);
                }
            } else {
                #pragma unroll
                for (int g = 0; g < 8; ++g) {
                    gh[g][0] = make_float2(0.f, 0.f);
                    gh[g][1] = make_float2(0.f, 0.f);
                }
            }
            const float* wb = &g_WhhT[(size_t)(Jbase + jh * 64) * KG + q4];
            const float* db = s_det8 + cur * 2048 + (jh * 64) * 16;
            #pragma unroll 4
            for (int jj = 0; jj < 64; ++jj) {
                float4 w = *(const float4*)(wb + (size_t)jj * KG);
                float2 wl = make_float2(w.x, w.y), wh2 = make_float2(w.z, w.w);
                float4 dA = *(const float4*)(db + jj * 16);
                float4 dB = *(const float4*)(db + jj * 16 + 4);
                float4 dC = *(const float4*)(db + jj * 16 + 8);
                float4 dD = *(const float4*)(db + jj * 16 + 12);
                float2 dp[8] = { make_float2(dA.x, dA.y), make_float2(dA.z, dA.w),
                                 make_float2(dB.x, dB.y), make_float2(dB.z, dB.w),
                                 make_float2(dC.x, dC.y), make_float2(dC.z, dC.w),
                                 make_float2(dD.x, dD.y), make_float2(dD.z, dD.w) };
                #pragma unroll
                for (int g = 0; g < 8; ++g) {
                    ffma2(gh[g][0], dp[g], wl);
                    ffma2(gh[g][1], dp[g], wh2);
                }
            }
            if (jh == 0) {
                #pragma unroll
                for (int g = 0; g < 8; ++g)
                    *(float4*)&s_gh8[g * KG + q4] =
                        make_float4(gh[g][0].x, gh[g][0].y, gh[g][1].x, gh[g][1].y);
            }
        }
        __syncthreads();
        // ---- 8. jh1 combines halves; peer-row rows also pushed to peer's s_ghr ----
        if (jh == 1 && lk < 192) {
            const int q4 = lk * 4;
            const int pb = (rank ^ 1) * 4;
            #pragma unroll
            for (int g = 0; g < 8; ++g) {
                float4 p = *(const float4*)&s_gh8[g * KG + q4];
                float4 c = make_float4(p.x + gh[g][0].x, p.y + gh[g][0].y,
                                       p.z + gh[g][1].x, p.w + gh[g][1].y);
                *(float4*)&s_gh8[g * KG + q4] = c;
                if (g >= pb && g < pb + 4)
                    *(float4*)&p_ghr[(g - pb) * KG + q4] = c;
            }
        }
        cluster.sync();   // CS1: gh partials exchanged

        // ---- 10. GRU for own rows + det distribution ----
        {
            const int u = lk;
            #pragma unroll
            for (int ii = 0; ii < 2; ++ii) {
                int i = jh * 2 + ii;          // own-local row
                int g = rank * 4 + i;         // pair-global row
                float ir = s_gi[i * KG + u];
                float hr = s_gh8[g * KG + u]       + s_ghr[i * KG + u];
                float iz = s_gi[i * KG + u + 256];
                float hz = s_gh8[g * KG + u + 256] + s_ghr[i * KG + u + 256];
                float in_ = s_gi[i * KG + u + 512];
                float hn = s_gh8[g * KG + u + 512] + s_ghr[i * KG + u + 512];
                float rg = 1.f / (1.f + expf(-(ir + hr)));
                float z  = 1.f / (1.f + expf(-(iz + hz)));
                float n  = tanhf(fmaf(rg, hn, in_));
                float dp = s_detown[cur * 1024 + i * 256 + u];
                float h  = (1.f - z) * n + z * dp;
                s_detown[(cur ^ 1) * 1024 + i * 256 + u] = h;
                float2 hh = make_float2(h, h);
                int jloc = u & 127;
                if ((u >> 7) == rank)
                    *(float2*)&s_det8[(cur ^ 1) * 2048 + jloc * 16 + 2 * g] = hh;
                else
                    *(float2*)&p_det8[(cur ^ 1) * 2048 + jloc * 16 + 2 * g] = hh;
                out[DET_OFF + ((size_t)(orow0 + i) * TT + t) * RR + u] = h;
            }
        }
        cluster.sync();   // CS2: new det slices exchanged

        // ---- 12. phase 2: logits partial over my j-slice (jh splits jj, 8 rows) ----
        float2 acc[8][2];
        {
            const int q4 = lk * 4;
            #pragma unroll
            for (int g = 0; g < 8; ++g) {
                acc[g][0] = make_float2(0.f, 0.f);
                acc[g][1] = make_float2(0.f, 0.f);
            }
            const float* wb = &g_WphT[(size_t)(Jbase + jh * 64) * LL + q4];
            const float* db = s_det8 + (cur ^ 1) * 2048 + (jh * 64) * 16;
            #pragma unroll 4
            for (int jj = 0; jj < 64; ++jj) {
                float4 w = *(const float4*)(wb + (size_t)jj * LL);
                float2 wl = make_float2(w.x, w.y), wh2 = make_float2(w.z, w.w);
                float4 dA = *(const float4*)(db + jj * 16);
                float4 dB = *(const float4*)(db + jj * 16 + 4);
                float4 dC = *(const float4*)(db + jj * 16 + 8);
                float4 dD = *(const float4*)(db + jj * 16 + 12);
                float2 dp[8] = { make_float2(dA.x, dA.y), make_float2(dA.z, dA.w),
                                 make_float2(dB.x, dB.y), make_float2(dB.z, dB.w),
                                 make_float2(dC.x, dC.y), make_float2(dC.z, dC.w),
                                 make_float2(dD.x, dD.y), make_float2(dD.z, dD.w) };
                #pragma unroll
                for (int g = 0; g < 8; ++g) {
                    ffma2(acc[g][0], dp[g], wl);
                    ffma2(acc[g][1], dp[g], wh2);
                }
            }
            if (jh == 0) {
                #pragma unroll
                for (int g = 0; g < 8; ++g)
                    *(float4*)&s_lg8[g * LL + q4] =
                        make_float4(acc[g][0].x, acc[g][0].y, acc[g][1].x, acc[g][1].y);
            }
        }
        __syncthreads();
        if (jh == 1) {
            const int q4 = lk * 4;
            const int pb = (rank ^ 1) * 4;
            #pragma unroll
            for (int g = 0; g < 8; ++g) {
                float4 p = *(const float4*)&s_lg8[g * LL + q4];
                float4 c = make_float4(p.x + acc[g][0].x, p.y + acc[g][0].y,
                                       p.z + acc[g][1].x, p.w + acc[g][1].y);
                *(float4*)&s_lg8[g * LL + q4] = c;
                if (g >= pb && g < pb + 4)
                    *(float4*)&p_lgr[(g - pb) * LL + q4] = c;
            }
        }
        cluster.sync();   // CS3: logits partials exchanged

        // ---- 16. finalize own rows: logits, gumbel argmax, one-hot stoch ----
        {
            const int q4 = lk * 4;
            #pragma unroll
            for (int ii = 0; ii < 2; ++ii) {
                int i = jh * 2 + ii;
                int g = rank * 4 + i;
                size_t bt = (size_t)(orow0 + i) * TT + t;
                float4 ob = *(const float4*)&out[LG_OFF + bt * LL + q4];  // obs part + b_post
                float4 pa = *(const float4*)&s_lg8[g * LL + q4];
                float4 pbv = *(const float4*)&s_lgr[i * LL + q4];
                float4 lg;
                lg.x = ob.x + pa.x + pbv.x; lg.y = ob.y + pa.y + pbv.y;
                lg.z = ob.z + pa.z + pbv.z; lg.w = ob.w + pa.w + pbv.w;
                *(float4*)&out[LG_OFF + bt * LL + q4] = lg;
                float4 g4 = *(const float4*)&gumbel[((size_t)t * BB + orow0 + i) * LL + q4];
                float v0 = lg.x + g4.x, v1 = lg.y + g4.y;
                float v2 = lg.z + g4.z, v3 = lg.w + g4.w;
                float bv = v0; int bi = q4;
                if (v1 > bv) { bv = v1; bi = q4 + 1; }
                if (v2 > bv) { bv = v2; bi = q4 + 2; }
                if (v3 > bv) { bv = v3; bi = q4 + 3; }
                #pragma unroll
                for (int off = 1; off < 8; off <<= 1) {
                    float ov = __shfl_xor_sync(0xffffffffu, bv, off);
                    int   oi = __shfl_xor_sync(0xffffffffu, bi, off);
                    if (ov > bv || (ov == bv && oi < bi)) { bv = ov; bi = oi; }
                }
                float4 sv;
                sv.x = (q4 + 0 == bi) ? 1.f : 0.f;
                sv.y = (q4 + 1 == bi) ? 1.f : 0.f;
                sv.z = (q4 + 2 == bi) ? 1.f : 0.f;
                sv.w = (q4 + 3 == bi) ? 1.f : 0.f;
                *(float4*)&out[ST_OFF + bt * LL + q4] = sv;
                if ((lk & 7) == 0) s_idx[i][lk >> 3] = bi & 31;
            }
        }
        cur ^= 1;
    }
}

// ---------------- launcher ----------------
extern "C" void kernel_launch(void* const* d_in, const int* in_sizes, int n_in,
                              void* d_out, int out_size) {
    const float* obs          = (const float*)d_in[0];
    const float* action       = (const float*)d_in[1];
    const unsigned int* first = (const unsigned int*)d_in[2];
    const float* gumbel       = (const float*)d_in[3];
    const float* W_in         = (const float*)d_in[4];
    const float* b_in         = (const float*)d_in[5];
    const float* W_ih         = (const float*)d_in[6];
    const float* W_hh         = (const float*)d_in[7];
    const float* b_ih         = (const float*)d_in[8];
    const float* b_hh         = (const float*)d_in[9];
    const float* W_post       = (const float*)d_in[10];
    const float* b_post       = (const float*)d_in[11];
    float* out = (float*)d_out;
    (void)in_sizes; (void)n_in; (void)out_size;

    static int smem_set = 0;
    if (!smem_set) {
        cudaFuncSetAttribute(scan_kernel, cudaFuncAttributeMaxDynamicSharedMemorySize,
                             SMEM_FLOATS * sizeof(float));
        smem_set = 1;
    }

    prep_fuse<<<(KG * 1031 + 255) / 256, 256>>>(W_in, b_in, W_ih, b_ih);
    prep_transpose<<<(KG * RR + LL * (RR + HH) + 255) / 256, 256>>>(W_hh, W_post);
    dim3 ggrid(LL / 64, (BB * TT) / 128);
    obs_gemm<<<ggrid, 256>>>(obs, b_post, out + LG_OFF);
    scan_kernel<<<NCTA, 512, SMEM_FLOATS * sizeof(float)>>>(action, first, gumbel, b_hh, out);
}

// round 9
// speedup vs baseline: 1.0830x; 1.0086x over previous
#include <cuda_runtime.h>
#include <cooperative_groups.h>
#include <cstdint>

namespace cg = cooperative_groups;

// ---------------- problem dims ----------------
#define BB 512
#define TT 64
#define HH 256     // hidden / obs dim
#define AA 6       // action dim
#define RR 256     // recurrent dim
#define KG 768     // 3*RR gate dim
#define LL 1024    // latent dim
#define NCTA 128   // CTAs (64 clusters of 2); each cluster owns 8 rows, each CTA owns 4

// output layout: [deter | stoch | logits]
#define DET_OFF 0
#define ST_OFF  (BB * TT * RR)
#define LG_OFF  (BB * TT * RR + BB * TT * LL)

// ---------------- device scratch ----------------
__device__ __align__(16) float g_WcT[LL * KG];     // [c][k] fused stoch weights
__device__ __align__(16) float g_WcaT[AA * KG];    // [j][k] fused action weights
__device__ __align__(16) float g_bc[KG];           // b_ih + W_ih @ b_in
__device__ __align__(16) float g_WhhT[RR * KG];    // [j][k]
__device__ __align__(16) float g_WphT[RR * LL];    // [j][l]
__device__ __align__(16) float g_WpoT[HH * LL];    // [k][n]

// ---------------- packed fp32 helpers (FFMA2 path) ----------------
__device__ __forceinline__ void ffma2(float2& d, const float2 a, const float2 b) {
    asm("fma.rn.f32x2 %0, %1, %2, %0;"
        : "+l"(reinterpret_cast<unsigned long long&>(d))
        : "l"(reinterpret_cast<const unsigned long long&>(a)),
          "l"(reinterpret_cast<const unsigned long long&>(b)));
}

// ---------------- prep 1: fuse W_ih @ [W_in | b_in] ----------------
__global__ void prep_fuse(const float* __restrict__ W_in, const float* __restrict__ b_in,
                          const float* __restrict__ W_ih, const float* __restrict__ b_ih) {
    int idx = blockIdx.x * blockDim.x + threadIdx.x;
    if (idx >= KG * 1031) return;
    int k = idx / 1031;
    int c = idx % 1031;
    float acc = 0.f;
    if (c < 1030) {
        for (int h = 0; h < HH; ++h)
            acc = fmaf(W_ih[k * HH + h], W_in[h * 1030 + c], acc);
        if (c < LL) g_WcT[c * KG + k] = acc;
        else        g_WcaT[(c - LL) * KG + k] = acc;
    } else {
        for (int h = 0; h < HH; ++h)
            acc = fmaf(W_ih[k * HH + h], b_in[h], acc);
        g_bc[k] = acc + b_ih[k];
    }
}

// ---------------- prep 2: transposes ----------------
__global__ void prep_transpose(const float* __restrict__ W_hh, const float* __restrict__ W_post) {
    int idx = blockIdx.x * blockDim.x + threadIdx.x;
    const int T1 = KG * RR;
    const int T2 = LL * (RR + HH);
    if (idx < T1) {
        int k = idx / RR, j = idx % RR;
        g_WhhT[j * KG + k] = W_hh[idx];
    } else if (idx < T1 + T2) {
        int e = idx - T1;
        int l = e / (RR + HH), m = e % (RR + HH);
        float v = W_post[e];
        if (m < RR) g_WphT[m * LL + l] = v;
        else        g_WpoT[(m - RR) * LL + l] = v;
    }
}

// ---------------- obs GEMM (proven: 128x64, BK=16, f32x2) ----------------
__global__ void __launch_bounds__(256) obs_gemm(const float* __restrict__ obs,
                                                const float* __restrict__ b_post,
                                                float* __restrict__ outL) {
    __shared__ float2 As2[128][17];   // duplicated {a,a}
    __shared__ float  Bs[16][64];
    int tid = threadIdx.x;
    int bm = blockIdx.y * 128;
    int bn = blockIdx.x * 64;
    int ty = tid >> 4;
    int tx = tid & 15;
    float2 acc2[8][2];
    #pragma unroll
    for (int i = 0; i < 8; ++i) { acc2[i][0] = make_float2(0.f, 0.f); acc2[i][1] = make_float2(0.f, 0.f); }

    for (int k0 = 0; k0 < HH; k0 += 16) {
        #pragma unroll
        for (int i = 0; i < 2; ++i) {
            int f = tid + i * 256;
            int row = f >> 2;
            int kp = (f & 3) * 4;
            float4 v = *(const float4*)&obs[(size_t)(bm + row) * HH + k0 + kp];
            As2[row][kp + 0] = make_float2(v.x, v.x);
            As2[row][kp + 1] = make_float2(v.y, v.y);
            As2[row][kp + 2] = make_float2(v.z, v.z);
            As2[row][kp + 3] = make_float2(v.w, v.w);
        }
        #pragma unroll
        for (int i = 0; i < 4; ++i) {
            int e = tid + i * 256;
            int kk = e >> 6;
            int n = e & 63;
            Bs[kk][n] = g_WpoT[(k0 + kk) * LL + bn + n];
        }
        __syncthreads();
        #pragma unroll
        for (int kk = 0; kk < 16; ++kk) {
            float2 b0 = *(const float2*)&Bs[kk][tx * 4];
            float2 b1 = *(const float2*)&Bs[kk][tx * 4 + 2];
            #pragma unroll
            for (int i = 0; i < 8; ++i) {
                float2 a2 = As2[ty * 8 + i][kk];
                ffma2(acc2[i][0], a2, b0);
                ffma2(acc2[i][1], a2, b1);
            }
        }
        __syncthreads();
    }
    float bp0 = b_post[bn + tx * 4], bp1 = b_post[bn + tx * 4 + 1];
    float bp2 = b_post[bn + tx * 4 + 2], bp3 = b_post[bn + tx * 4 + 3];
    #pragma unroll
    for (int i = 0; i < 8; ++i) {
        int m = bm + ty * 8 + i;
        float4 v;
        v.x = acc2[i][0].x + bp0; v.y = acc2[i][0].y + bp1;
        v.z = acc2[i][1].x + bp2; v.w = acc2[i][1].y + bp3;
        *(float4*)&outL[(size_t)m * LL + bn + tx * 4] = v;
    }
}

// ---------------- cluster-2 persistent scan (round-7 reset + 8-deep prefetch) ----------------
#define OFF_GI     0
#define OFF_GH8    3072
#define OFF_GHR    9216
#define OFF_DET8   12288
#define OFF_DETOWN 16384
#define OFF_LG8    18432
#define OFF_LGR    26624
#define SMEM_FLOATS 30720

__global__ void __launch_bounds__(512, 1) __cluster_dims__(2, 1, 1)
scan_kernel(const float* __restrict__ action,
            const unsigned int* __restrict__ first,
            const float* __restrict__ gumbel,       // [T][B][1024]
            const float* __restrict__ b_hh,
            float* __restrict__ out) {

    extern __shared__ float smem[];
    float* s_gi     = smem + OFF_GI;
    float* s_gh8    = smem + OFF_GH8;
    float* s_ghr    = smem + OFF_GHR;
    float* s_det8   = smem + OFF_DET8;
    float* s_detown = smem + OFF_DETOWN;
    float* s_lg8    = smem + OFF_LG8;
    float* s_lgr    = smem + OFF_LGR;
    __shared__ int   s_idx[4][32];
    __shared__ float s_act[4][AA];
    __shared__ int   s_reset[8];     // pair-global rows, first[t]

    cg::cluster_group cluster = cg::this_cluster();
    const int rank = (int)cluster.block_rank();
    float* p_ghr  = (float*)cluster.map_shared_rank(s_ghr,  rank ^ 1);
    float* p_det8 = (float*)cluster.map_shared_rank(s_det8, rank ^ 1);
    float* p_lgr  = (float*)cluster.map_shared_rank(s_lgr,  rank ^ 1);

    const int tid = threadIdx.x;
    const int jh  = tid >> 8;        // intra-CTA jj-half
    const int lk  = tid & 255;
    const int pair  = blockIdx.x >> 1;
    const int prow0 = pair * 8;
    const int orow0 = prow0 + rank * 4;      // own rows base
    const int Jbase = rank * 128;            // this CTA's j slice
    int cur = 0;

    for (int t = 0; t < TT; ++t) {
        // ---- flags (all 8 rows) + action (own rows) ----
        if (tid < 8) {
            unsigned f = first[(prow0 + tid) * TT + t];
            s_reset[tid] = (t == 0) || (f != 0u);
        }
        if (tid >= 32 && tid < 32 + 4 * AA) {
            int e = tid - 32;
            s_act[e / AA][e % AA] = action[((size_t)(orow0 + e / AA) * TT + t) * AA + (e % AA)];
        }
        __syncthreads();

        // ---- zero carries on reset (det8 slice: all 8 rows; detown: own rows) ----
        #pragma unroll
        for (int k = 0; k < 2; ++k) {
            int idx = tid + k * 512;       // 1024 items: det8 slice
            int jj = idx >> 3, g = idx & 7;
            if (s_reset[g])
                *(float2*)&s_det8[cur * 2048 + jj * 16 + 2 * g] = make_float2(0.f, 0.f);
        }
        #pragma unroll
        for (int k = 0; k < 2; ++k) {
            int idx = tid + k * 512;       // 1024 items: detown
            int r = idx >> 8, u = idx & 255;
            if (s_reset[rank * 4 + r])
                s_detown[cur * 1024 + r * 256 + u] = 0.f;
        }
        __syncthreads();

        // ---- gi for own rows (bias + action + one-hot gather) ----
        for (int item = tid; item < 4 * 192; item += 512) {
            int r = item / 192;
            int q = (item % 192) * 4;
            float4 a4 = *(const float4*)&g_bc[q];
            #pragma unroll
            for (int j = 0; j < AA; ++j) {
                float av = s_act[r][j];
                float4 w = *(const float4*)&g_WcaT[j * KG + q];
                a4.x = fmaf(av, w.x, a4.x); a4.y = fmaf(av, w.y, a4.y);
                a4.z = fmaf(av, w.z, a4.z); a4.w = fmaf(av, w.w, a4.w);
            }
            if (!s_reset[rank * 4 + r]) {
                #pragma unroll 8
                for (int g = 0; g < 32; ++g) {
                    int c = (g << 5) + s_idx[r][g];
                    float4 w = *(const float4*)&g_WcT[c * KG + q];
                    a4.x += w.x; a4.y += w.y; a4.z += w.z; a4.w += w.w;
                }
            }
            *(float4*)&s_gi[r * KG + q] = a4;
        }

        // ---- phase 1: gh partial over my j-slice (8-deep weight prefetch) ----
        float2 gh[8][2];
        if (lk < 192) {
            const int q4 = lk * 4;
            if (rank == 0 && jh == 0) {
                float4 bh = *(const float4*)&b_hh[q4];
                #pragma unroll
                for (int g = 0; g < 8; ++g) {
                    gh[g][0] = make_float2(bh.x, bh.y);
                    gh[g][1] = make_float2(bh.z, bh.w);
                }
            } else {
                #pragma unroll
                for (int g = 0; g < 8; ++g) {
                    gh[g][0] = make_float2(0.f, 0.f);
                    gh[g][1] = make_float2(0.f, 0.f);
                }
            }
            const float4* wp  = (const float4*)&g_WhhT[(size_t)(Jbase + jh * 64) * KG + q4];
            const size_t  WS  = KG / 4;
            const float4* db4 = (const float4*)(s_det8 + cur * 2048 + (jh * 64) * 16);
            float4 wb8[8];
            #pragma unroll
            for (int p = 0; p < 8; ++p) wb8[p] = wp[(size_t)p * WS];
            #pragma unroll 1
            for (int base = 0; base < 64; base += 8) {
                #pragma unroll
                for (int p = 0; p < 8; ++p) {
                    float4 w = wb8[p];
                    int nj = base + 8 + p; nj = (nj < 64) ? nj : 63;
                    wb8[p] = wp[(size_t)nj * WS];
                    const float4* dq = db4 + (size_t)(base + p) * 4;
                    float4 dA = dq[0], dB = dq[1], dC = dq[2], dD = dq[3];
                    float2 wl = make_float2(w.x, w.y), wh2 = make_float2(w.z, w.w);
                    float2 dp[8] = { make_float2(dA.x, dA.y), make_float2(dA.z, dA.w),
                                     make_float2(dB.x, dB.y), make_float2(dB.z, dB.w),
                                     make_float2(dC.x, dC.y), make_float2(dC.z, dC.w),
                                     make_float2(dD.x, dD.y), make_float2(dD.z, dD.w) };
                    #pragma unroll
                    for (int g = 0; g < 8; ++g) {
                        ffma2(gh[g][0], dp[g], wl);
                        ffma2(gh[g][1], dp[g], wh2);
                    }
                }
            }
            if (jh == 0) {
                #pragma unroll
                for (int g = 0; g < 8; ++g)
                    *(float4*)&s_gh8[g * KG + q4] =
                        make_float4(gh[g][0].x, gh[g][0].y, gh[g][1].x, gh[g][1].y);
            }
        }
        __syncthreads();
        if (jh == 1 && lk < 192) {   // combine halves; push peer rows to peer's s_ghr
            const int q4 = lk * 4;
            const int pb = (rank ^ 1) * 4;
            #pragma unroll
            for (int g = 0; g < 8; ++g) {
                float4 p = *(const float4*)&s_gh8[g * KG + q4];
                float4 c = make_float4(p.x + gh[g][0].x, p.y + gh[g][0].y,
                                       p.z + gh[g][1].x, p.w + gh[g][1].y);
                *(float4*)&s_gh8[g * KG + q4] = c;
                if (g >= pb && g < pb + 4)
                    *(float4*)&p_ghr[(g - pb) * KG + q4] = c;
            }
        }
        cluster.sync();   // CS1: gh partials exchanged

        // ---- GRU for own rows + det distribution (true h everywhere) ----
        {
            const int u = lk;
            #pragma unroll
            for (int ii = 0; ii < 2; ++ii) {
                int i = jh * 2 + ii;          // own-local row
                int g = rank * 4 + i;         // pair-global row
                float ir = s_gi[i * KG + u];
                float hr = s_gh8[g * KG + u]       + s_ghr[i * KG + u];
                float iz = s_gi[i * KG + u + 256];
                float hz = s_gh8[g * KG + u + 256] + s_ghr[i * KG + u + 256];
                float in_ = s_gi[i * KG + u + 512];
                float hn = s_gh8[g * KG + u + 512] + s_ghr[i * KG + u + 512];
                float rg = 1.f / (1.f + expf(-(ir + hr)));
                float z  = 1.f / (1.f + expf(-(iz + hz)));
                float n  = tanhf(fmaf(rg, hn, in_));
                float dp = s_detown[cur * 1024 + i * 256 + u];
                float h  = (1.f - z) * n + z * dp;
                s_detown[(cur ^ 1) * 1024 + i * 256 + u] = h;
                float2 hh = make_float2(h, h);
                int jloc = u & 127;
                if ((u >> 7) == rank)
                    *(float2*)&s_det8[(cur ^ 1) * 2048 + jloc * 16 + 2 * g] = hh;
                else
                    *(float2*)&p_det8[(cur ^ 1) * 2048 + jloc * 16 + 2 * g] = hh;
                out[DET_OFF + ((size_t)(orow0 + i) * TT + t) * RR + u] = h;
            }
        }
        cluster.sync();   // CS2: new det slices exchanged

        // ---- phase 2: logits partial over my j-slice (8-deep weight prefetch) ----
        float2 acc[8][2];
        {
            const int q4 = lk * 4;
            #pragma unroll
            for (int g = 0; g < 8; ++g) {
                acc[g][0] = make_float2(0.f, 0.f);
                acc[g][1] = make_float2(0.f, 0.f);
            }
            const float4* wp  = (const float4*)&g_WphT[(size_t)(Jbase + jh * 64) * LL + q4];
            const size_t  WS  = LL / 4;
            const float4* db4 = (const float4*)(s_det8 + (cur ^ 1) * 2048 + (jh * 64) * 16);
            float4 wb8[8];
            #pragma unroll
            for (int p = 0; p < 8; ++p) wb8[p] = wp[(size_t)p * WS];
            #pragma unroll 1
            for (int base = 0; base < 64; base += 8) {
                #pragma unroll
                for (int p = 0; p < 8; ++p) {
                    float4 w = wb8[p];
                    int nj = base + 8 + p; nj = (nj < 64) ? nj : 63;
                    wb8[p] = wp[(size_t)nj * WS];
                    const float4* dq = db4 + (size_t)(base + p) * 4;
                    float4 dA = dq[0], dB = dq[1], dC = dq[2], dD = dq[3];
                    float2 wl = make_float2(w.x, w.y), wh2 = make_float2(w.z, w.w);
                    float2 dp[8] = { make_float2(dA.x, dA.y), make_float2(dA.z, dA.w),
                                     make_float2(dB.x, dB.y), make_float2(dB.z, dB.w),
                                     make_float2(dC.x, dC.y), make_float2(dC.z, dC.w),
                                     make_float2(dD.x, dD.y), make_float2(dD.z, dD.w) };
                    #pragma unroll
                    for (int g = 0; g < 8; ++g) {
                        ffma2(acc[g][0], dp[g], wl);
                        ffma2(acc[g][1], dp[g], wh2);
                    }
                }
            }
            if (jh == 0) {
                #pragma unroll
                for (int g = 0; g < 8; ++g)
                    *(float4*)&s_lg8[g * LL + q4] =
                        make_float4(acc[g][0].x, acc[g][0].y, acc[g][1].x, acc[g][1].y);
            }
        }
        __syncthreads();
        if (jh == 1) {
            const int q4 = lk * 4;
            const int pb = (rank ^ 1) * 4;
            #pragma unroll
            for (int g = 0; g < 8; ++g) {
                float4 p = *(const float4*)&s_lg8[g * LL + q4];
                float4 c = make_float4(p.x + acc[g][0].x, p.y + acc[g][0].y,
                                       p.z + acc[g][1].x, p.w + acc[g][1].y);
                *(float4*)&s_lg8[g * LL + q4] = c;
                if (g >= pb && g < pb + 4)
                    *(float4*)&p_lgr[(g - pb) * LL + q4] = c;
            }
        }
        cluster.sync();   // CS3: logits partials exchanged

        // ---- finalize own rows: logits, gumbel argmax, one-hot stoch ----
        {
            const int q4 = lk * 4;
            #pragma unroll
            for (int ii = 0; ii < 2; ++ii) {
                int i = jh * 2 + ii;
                int g = rank * 4 + i;
                size_t bt = (size_t)(orow0 + i) * TT + t;
                float4 ob = *(const float4*)&out[LG_OFF + bt * LL + q4];  // obs part + b_post
                float4 pa = *(const float4*)&s_lg8[g * LL + q4];
                float4 pbv = *(const float4*)&s_lgr[i * LL + q4];
                float4 lg;
                lg.x = ob.x + pa.x + pbv.x; lg.y = ob.y + pa.y + pbv.y;
                lg.z = ob.z + pa.z + pbv.z; lg.w = ob.w + pa.w + pbv.w;
                *(float4*)&out[LG_OFF + bt * LL + q4] = lg;
                float4 g4 = *(const float4*)&gumbel[((size_t)t * BB + orow0 + i) * LL + q4];
                float v0 = lg.x + g4.x, v1 = lg.y + g4.y;
                float v2 = lg.z + g4.z, v3 = lg.w + g4.w;
                float bv = v0; int bi = q4;
                if (v1 > bv) { bv = v1; bi = q4 + 1; }
                if (v2 > bv) { bv = v2; bi = q4 + 2; }
                if (v3 > bv) { bv = v3; bi = q4 + 3; }
                #pragma unroll
                for (int off = 1; off < 8; off <<= 1) {
                    float ov = __shfl_xor_sync(0xffffffffu, bv, off);
                    int   oi = __shfl_xor_sync(0xffffffffu, bi, off);
                    if (ov > bv || (ov == bv && oi < bi)) { bv = ov; bi = oi; }
                }
                float4 sv;
                sv.x = (q4 + 0 == bi) ? 1.f : 0.f;
                sv.y = (q4 + 1 == bi) ? 1.f : 0.f;
                sv.z = (q4 + 2 == bi) ? 1.f : 0.f;
                sv.w = (q4 + 3 == bi) ? 1.f : 0.f;
                *(float4*)&out[ST_OFF + bt * LL + q4] = sv;
                if ((lk & 7) == 0) s_idx[i][lk >> 3] = bi & 31;
            }
        }
        cur ^= 1;
    }
}

// ---------------- launcher ----------------
extern "C" void kernel_launch(void* const* d_in, const int* in_sizes, int n_in,
                              void* d_out, int out_size) {
    const float* obs          = (const float*)d_in[0];
    const float* action       = (const float*)d_in[1];
    const unsigned int* first = (const unsigned int*)d_in[2];
    const float* gumbel       = (const float*)d_in[3];
    const float* W_in         = (const float*)d_in[4];
    const float* b_in         = (const float*)d_in[5];
    const float* W_ih         = (const float*)d_in[6];
    const float* W_hh         = (const float*)d_in[7];
    const float* b_ih         = (const float*)d_in[8];
    const float* b_hh         = (const float*)d_in[9];
    const float* W_post       = (const float*)d_in[10];
    const float* b_post       = (const float*)d_in[11];
    float* out = (float*)d_out;
    (void)in_sizes; (void)n_in; (void)out_size;

    static int smem_set = 0;
    if (!smem_set) {
        cudaFuncSetAttribute(scan_kernel, cudaFuncAttributeMaxDynamicSharedMemorySize,
                             SMEM_FLOATS * sizeof(float));
        smem_set = 1;
    }

    prep_fuse<<<(KG * 1031 + 255) / 256, 256>>>(W_in, b_in, W_ih, b_ih);
    prep_transpose<<<(KG * RR + LL * (RR + HH) + 255) / 256, 256>>>(W_hh, W_post);
    dim3 ggrid(LL / 64, (BB * TT) / 128);
    obs_gemm<<<ggrid, 256>>>(obs, b_post, out + LG_OFF);
    scan_kernel<<<NCTA, 512, SMEM_FLOATS * sizeof(float)>>>(action, first, gumbel, b_hh, out);
}